// round 12
// baseline (speedup 1.0000x reference)
#include <cuda_runtime.h>
#include <cstdint>

// CorrelationHead fused. Raw-layout smem via cp.async.bulk, 4-chunk c-pipeline,
// FFMA2 (fma.rn.f32x2) compute, W prefetched to registers.
// out[b,o] = bias[o] + sum over 625 in-bounds (i,j,u,v):
//   W[o, p*1029+q*49+i*7+j] * dot_c( P1[b,c,i,j], P2[b,c,u,v] ),
//   u = i+2(p-10), v = j+2(q-10) in [0,6]; u≡i (mod 2), v≡j (mod 2).
//
// tid = slot*4 + cs. slot = r*4 + ijq, r = (v&1)*7 + u (14 rows). c = cs + 4*cl.
// Per iter: 8 LDS.32 + 6 packs + 8 FFMA2 (= 16 fp32 FMAs: 4 ij x 4 v).

static constexpr int FEAT   = 21609;          // 21*21*49
static constexpr int TEN    = 6272;           // 128*49 floats per tensor per batch
static constexpr int CH_F   = TEN / 4;        // 1568 floats per c-quarter
static constexpr int CH_B   = CH_F * 4;       // 6272 bytes
static constexpr int S2_OFF   = TEN;
static constexpr int WRED_OFF = 2 * TEN + 16;          // 16-float pad absorbs y OOB tap
static constexpr int MBAR_B   = (WRED_OFF + 32) * 4;   // byte offset of mbarriers
static constexpr int SMEM_BYTES = MBAR_B + 32;         // four 8B mbarriers

__global__ __launch_bounds__(224, 4)
void corr_head_kernel(const float* __restrict__ p1,
                      const float* __restrict__ p2,
                      const float* __restrict__ W,
                      const float* __restrict__ bias,
                      float* __restrict__ out)
{
    extern __shared__ float sm[];
    float* s1   = sm;             // P1 raw: [c*49 + uv]
    float* s2   = sm + S2_OFF;    // P2 raw: [c*49 + uv]
    float* wred = sm + WRED_OFF;  // 7 warps * 4 outputs

    uint32_t smem_u32;
    asm("{ .reg .u64 t; cvta.to.shared.u64 t, %1; cvt.u32.u64 %0, t; }"
        : "=r"(smem_u32) : "l"(sm));

    const int b   = blockIdx.x;
    const int tid = threadIdx.x;
    const float* p1b = p1 + (size_t)b * TEN;
    const float* p2b = p2 + (size_t)b * TEN;

    // ---- Init 4 mbarriers (one per c-quarter); zero the OOB pad ----
    if (tid < 4) {
        asm volatile("mbarrier.init.shared.b64 [%0], 1;"
                     :: "r"(smem_u32 + MBAR_B + 8 * tid) : "memory");
    }
    if (tid >= 8 && tid < 24) sm[2 * TEN + (tid - 8)] = 0.f;
    __syncthreads();

    // ---- Issue all 8 bulk copies up front (2 tensors x 4 c-quarters) ----
    if (tid == 0) {
        const uint32_t d1 = smem_u32;
        const uint32_t d2 = smem_u32 + TEN * 4;
        #pragma unroll
        for (int k = 0; k < 4; k++) {
            const uint32_t mb = smem_u32 + MBAR_B + 8 * k;
            asm volatile("mbarrier.arrive.expect_tx.shared.b64 _, [%0], %1;"
                         :: "r"(mb), "r"(2 * CH_B) : "memory");
            asm volatile("cp.async.bulk.shared::cluster.global.mbarrier::complete_tx::bytes [%0], [%1], %2, [%3];"
                         :: "r"(d1 + k * CH_B), "l"(p1b + k * CH_F), "r"(CH_B), "r"(mb) : "memory");
            asm volatile("cp.async.bulk.shared::cluster.global.mbarrier::complete_tx::bytes [%0], [%1], %2, [%3];"
                         :: "r"(d2 + k * CH_B), "l"(p2b + k * CH_F), "r"(CH_B), "r"(mb) : "memory");
        }
    }

    // ---- Per-thread geometry ----
    const int cs   = tid & 3;
    const int slot = tid >> 2;          // 0..55
    const int r    = slot >> 2;         // 0..13
    const int ijq  = slot & 3;
    const int jpar = (r >= 7) ? 1 : 0;
    const int u    = r - jpar * 7;
    const int ipar = u & 1;
    const int ni   = 4 - ipar;
    const int nj   = 4 - jpar;
    const int nvi  = 4 - jpar;

    int xb[4];
    #pragma unroll
    for (int t = 0; t < 4; t++) {
        int idx = ijq * 4 + t;
        int a_  = (nj == 4) ? (idx >> 2) : (idx / 3);
        int b_  = idx - a_ * nj;
        int ij  = (ipar + 2 * a_) * 7 + (jpar + 2 * b_);
        xb[t]   = ((idx < ni * nj) ? ij : 0) + cs * 49;
    }
    const int yb = u * 7 + jpar + cs * 49;

    // ---- Prefetch W into registers (overlaps the in-flight bulk copies) ----
    float wv[16];
    {
        const float* Wo = W + cs * FEAT;
        #pragma unroll
        for (int t = 0; t < 4; t++) {
            int idx = ijq * 4 + t;
            bool val = idx < ni * nj;
            int a_  = (nj == 4) ? (idx >> 2) : (idx / 3);
            int b_  = idx - a_ * nj;
            int ij  = (ipar + 2 * a_) * 7 + (jpar + 2 * b_);
            int wb  = (10 + (u >> 1) - a_) * 1029 + (10 - b_) * 49 + ij;
            wv[t*4+0] = val ? __ldg(Wo + wb)       : 0.f;
            wv[t*4+1] = val ? __ldg(Wo + wb + 49)  : 0.f;
            wv[t*4+2] = val ? __ldg(Wo + wb + 98)  : 0.f;
            wv[t*4+3] = (val && nvi == 4) ? __ldg(Wo + wb + 147) : 0.f;
        }
    }

    // ---- Accumulators: b64 pairs over v-taps: aT0 = (dotT.x, dotT.y), aT1 = (.z,.w) ----
    unsigned long long a00 = 0ull, a01 = 0ull, a10 = 0ull, a11 = 0ull,
                       a20 = 0ull, a21 = 0ull, a30 = 0ull, a31 = 0ull;

    #define PACK2(d, lo, hi) \
        asm("mov.b64 %0, {%1, %2};" : "=l"(d) : "f"(lo), "f"(hi))
    #define FFMA2(acc, aa, bb) \
        asm("fma.rn.f32x2 %0, %1, %2, %3;" : "=l"(acc) : "l"(aa), "l"(bb), "l"(acc))

    #define MBAR_WAIT(mb) do {                                                    \
        asm volatile("{\n\t.reg .pred P;\n\t"                                     \
                     "WL_%=:\n\t"                                                 \
                     "mbarrier.try_wait.parity.acquire.cta.shared::cta.b64 P, [%0], 0, 0x989680;\n\t" \
                     "@!P bra WL_%=;\n\t}"                                        \
                     :: "r"(mb) : "memory");                                      \
    } while (0)

    #define BODY(cl) do {                                                         \
        const int off = (cl) * 196;                                               \
        float y0 = s2[yb + off];                                                  \
        float y1 = s2[yb + off + 2];                                              \
        float y2 = s2[yb + off + 4];                                              \
        float y3 = s2[yb + off + 6];                                              \
        float x0 = s1[xb[0] + off];                                               \
        float x1 = s1[xb[1] + off];                                               \
        float x2 = s1[xb[2] + off];                                               \
        float x3 = s1[xb[3] + off];                                               \
        unsigned long long yp01, yp23, xd0, xd1, xd2, xd3;                        \
        PACK2(yp01, y0, y1);  PACK2(yp23, y2, y3);                                \
        PACK2(xd0, x0, x0);   PACK2(xd1, x1, x1);                                 \
        PACK2(xd2, x2, x2);   PACK2(xd3, x3, x3);                                 \
        FFMA2(a00, xd0, yp01); FFMA2(a01, xd0, yp23);                             \
        FFMA2(a10, xd1, yp01); FFMA2(a11, xd1, yp23);                             \
        FFMA2(a20, xd2, yp01); FFMA2(a21, xd2, yp23);                             \
        FFMA2(a30, xd3, yp01); FFMA2(a31, xd3, yp23);                             \
    } while (0)

    // ---- 4-chunk pipeline: wait quarter k, compute cl = 8k..8k+7 ----
    MBAR_WAIT(smem_u32 + MBAR_B);
    #pragma unroll
    for (int cl = 0; cl < 8; cl++) BODY(cl);
    MBAR_WAIT(smem_u32 + MBAR_B + 8);
    #pragma unroll
    for (int cl = 8; cl < 16; cl++) BODY(cl);
    MBAR_WAIT(smem_u32 + MBAR_B + 16);
    #pragma unroll
    for (int cl = 16; cl < 24; cl++) BODY(cl);
    MBAR_WAIT(smem_u32 + MBAR_B + 24);
    #pragma unroll
    for (int cl = 24; cl < 32; cl++) BODY(cl);

    #undef BODY
    #undef MBAR_WAIT

    // ---- Unpack b64 accumulators back to float4 dots ----
    float4 dot0, dot1, dot2, dot3;
    #define UNPK(v, lo, hi) asm("mov.b64 {%0, %1}, %2;" : "=f"(lo), "=f"(hi) : "l"(v))
    UNPK(a00, dot0.x, dot0.y); UNPK(a01, dot0.z, dot0.w);
    UNPK(a10, dot1.x, dot1.y); UNPK(a11, dot1.z, dot1.w);
    UNPK(a20, dot2.x, dot2.y); UNPK(a21, dot2.z, dot2.w);
    UNPK(a30, dot3.x, dot3.y); UNPK(a31, dot3.z, dot3.w);
    #undef UNPK
    #undef PACK2
    #undef FFMA2

    // ---- Reduce partial dots across the 4 cs lanes ----
    const unsigned FULL = 0xffffffffu;
    #pragma unroll
    for (int off = 1; off < 4; off <<= 1) {
        dot0.x += __shfl_xor_sync(FULL, dot0.x, off);
        dot0.y += __shfl_xor_sync(FULL, dot0.y, off);
        dot0.z += __shfl_xor_sync(FULL, dot0.z, off);
        dot0.w += __shfl_xor_sync(FULL, dot0.w, off);
        dot1.x += __shfl_xor_sync(FULL, dot1.x, off);
        dot1.y += __shfl_xor_sync(FULL, dot1.y, off);
        dot1.z += __shfl_xor_sync(FULL, dot1.z, off);
        dot1.w += __shfl_xor_sync(FULL, dot1.w, off);
        dot2.x += __shfl_xor_sync(FULL, dot2.x, off);
        dot2.y += __shfl_xor_sync(FULL, dot2.y, off);
        dot2.z += __shfl_xor_sync(FULL, dot2.z, off);
        dot2.w += __shfl_xor_sync(FULL, dot2.w, off);
        dot3.x += __shfl_xor_sync(FULL, dot3.x, off);
        dot3.y += __shfl_xor_sync(FULL, dot3.y, off);
        dot3.z += __shfl_xor_sync(FULL, dot3.z, off);
        dot3.w += __shfl_xor_sync(FULL, dot3.w, off);
    }

    // ---- Epilogue: branchless W combine (invalid/unused taps have wv = 0) ----
    float part = 0.f;
    part = fmaf(dot0.x, wv[0],  part); part = fmaf(dot0.y, wv[1],  part);
    part = fmaf(dot0.z, wv[2],  part); part = fmaf(dot0.w, wv[3],  part);
    part = fmaf(dot1.x, wv[4],  part); part = fmaf(dot1.y, wv[5],  part);
    part = fmaf(dot1.z, wv[6],  part); part = fmaf(dot1.w, wv[7],  part);
    part = fmaf(dot2.x, wv[8],  part); part = fmaf(dot2.y, wv[9],  part);
    part = fmaf(dot2.z, wv[10], part); part = fmaf(dot2.w, wv[11], part);
    part = fmaf(dot3.x, wv[12], part); part = fmaf(dot3.y, wv[13], part);
    part = fmaf(dot3.z, wv[14], part); part = fmaf(dot3.w, wv[15], part);

    // ---- Combine: 8 slots per warp via shfl, then 7 warps via smem ----
    part += __shfl_down_sync(FULL, part, 4);
    part += __shfl_down_sync(FULL, part, 8);
    part += __shfl_down_sync(FULL, part, 16);
    const int lane = tid & 31;
    if (lane < 4) wred[(tid >> 5) * 4 + lane] = part;   // lane == cs == o here
    __syncthreads();

    if (tid < 4) {
        float s = __ldg(bias + tid);
        #pragma unroll
        for (int w = 0; w < 7; w++) s += wred[w * 4 + tid];
        out[b * 4 + tid] = s;
    }
}

extern "C" void kernel_launch(void* const* d_in, const int* in_sizes, int n_in,
                              void* d_out, int out_size)
{
    (void)in_sizes; (void)n_in; (void)out_size;
    const float* p1 = (const float*)d_in[0];   // patch1 [512,128,7,7]
    const float* p2 = (const float*)d_in[1];   // patch2 [512,128,7,7]
    const float* W  = (const float*)d_in[2];   // w_bbox [4,21609]
    const float* bb = (const float*)d_in[3];   // b_bbox [4]
    float* out = (float*)d_out;                // [512,4] fp32

    cudaFuncSetAttribute(corr_head_kernel,
                         cudaFuncAttributeMaxDynamicSharedMemorySize, SMEM_BYTES);

    corr_head_kernel<<<512, 224, SMEM_BYTES>>>(p1, p2, W, bb, out);
}